// round 14
// baseline (speedup 1.0000x reference)
#include <cuda_runtime.h>

// MaxPool 2x2 stride 2, (16,64,512,512) fp32 -> (16,64,256,256) fp32.
// FINAL — session best: 186.14us harness, 7297 GB/s (92% of 8TB/s HBM spec).
//
// DRAM-interface bound: 13 rounds of measurement show every sane variant of
// this stream lands at 90.2-92.2% DRAM active / 186.1-186.9us. Decisive
// experiment: replacing 4x LDG.128 with 2x LDG.256 halved L1tex work
// (L1 38.7%->22.3%) with ZERO duration change -> SM side is irrelevant,
// the 4:1 mixed read/write DRAM stream alone sets the time. Remaining ~8%
// gap to spec = bus turnaround/refresh, unreachable from SASS.
//
// Config: one thread -> one float4 output via 4x coalesced LDG.128 (__ldcg:
// L2-only, stream-once data) + 1x STG.128. 64-thread CTAs (262,144 blocks):
// many tiny CTAs let the HW rasterizer supply deep free MLP (persistent
// 1-wave grid measured 204.9us; spread 64B/thread loads 188.4us; all cache-
// hint/layout/vector-width/grain variants within noise).

#define IN_H 512
#define OUT_H 256
#define BC (16 * 64)

#define IN_ROW_F4 128   // 512 floats / 4
#define OUT_ROW_F4 64   // 256 floats / 4

__global__ void maxpool2x2_kernel(const float4* __restrict__ in4,
                                  float4* __restrict__ out4) {
    unsigned tid = blockIdx.x * blockDim.x + threadIdx.x;

    unsigned ox4  = tid & (OUT_ROW_F4 - 1);         // [0, 64)
    unsigned rest = tid >> 6;
    unsigned oy   = rest & (OUT_H - 1);             // [0, 256)
    unsigned bc   = rest >> 8;                      // [0, 1024)

    unsigned ibase = bc * (IN_H * IN_ROW_F4) + (oy * 2) * IN_ROW_F4 + ox4 * 2;

    float4 r0a = __ldcg(&in4[ibase]);
    float4 r0b = __ldcg(&in4[ibase + 1]);
    float4 r1a = __ldcg(&in4[ibase + IN_ROW_F4]);
    float4 r1b = __ldcg(&in4[ibase + IN_ROW_F4 + 1]);

    float4 o;
    o.x = fmaxf(fmaxf(r0a.x, r0a.y), fmaxf(r1a.x, r1a.y));
    o.y = fmaxf(fmaxf(r0a.z, r0a.w), fmaxf(r1a.z, r1a.w));
    o.z = fmaxf(fmaxf(r0b.x, r0b.y), fmaxf(r1b.x, r1b.y));
    o.w = fmaxf(fmaxf(r0b.z, r0b.w), fmaxf(r1b.z, r1b.w));

    out4[tid] = o;
}

extern "C" void kernel_launch(void* const* d_in, const int* in_sizes, int n_in,
                              void* d_out, int out_size) {
    const float4* in4 = (const float4*)d_in[0];
    float4* out4 = (float4*)d_out;

    const unsigned total = (unsigned)BC * OUT_H * OUT_ROW_F4;  // 16,777,216
    const int threads = 64;
    const unsigned blocks = total / threads;                   // 262,144

    maxpool2x2_kernel<<<blocks, threads>>>(in4, out4);
}

// round 15
// speedup vs baseline: 1.0014x; 1.0014x over previous
#include <cuda_runtime.h>

// MaxPool 2x2 stride 2, (16,64,512,512) fp32 -> (16,64,256,256) fp32.
// FINAL — converged. 7294 GB/s (92.0% of 8TB/s HBM spec), ncu 181.5us,
// harness 186.1-186.8us across 4 samples of this exact binary.
//
// DRAM-interface bound, proven by controlled experiment: halving all load
// instructions (LDG.256, L1 38.7%->22.3%) changed duration by ZERO. Bytes
// are irreducible (1.34GB stream-once, no reuse); compute <7% busy; the
// ~8% gap to spec is 4:1 read/write bus turnaround + refresh, unreachable
// from SASS.
//
// Config: one thread -> one float4 output via 4x coalesced LDG.128 (__ldcg,
// L2-only for stream-once data) + 1x STG.128; 64-thread CTAs (262,144
// blocks) so the HW rasterizer supplies deep free MLP.
//
// Measured and rejected: persistent 1-wave grid (204.9us), 64B/thread
// spread loads (188.4us), f2-out / warp-row-pair / MLP8 layouts, __stcs/
// __ldcs hints, 256/128-thr grains, LDG.256 — all within noise or worse.

#define IN_H 512
#define OUT_H 256
#define BC (16 * 64)

#define IN_ROW_F4 128   // 512 floats / 4
#define OUT_ROW_F4 64   // 256 floats / 4

__global__ void maxpool2x2_kernel(const float4* __restrict__ in4,
                                  float4* __restrict__ out4) {
    unsigned tid = blockIdx.x * blockDim.x + threadIdx.x;

    unsigned ox4  = tid & (OUT_ROW_F4 - 1);         // [0, 64)
    unsigned rest = tid >> 6;
    unsigned oy   = rest & (OUT_H - 1);             // [0, 256)
    unsigned bc   = rest >> 8;                      // [0, 1024)

    unsigned ibase = bc * (IN_H * IN_ROW_F4) + (oy * 2) * IN_ROW_F4 + ox4 * 2;

    float4 r0a = __ldcg(&in4[ibase]);
    float4 r0b = __ldcg(&in4[ibase + 1]);
    float4 r1a = __ldcg(&in4[ibase + IN_ROW_F4]);
    float4 r1b = __ldcg(&in4[ibase + IN_ROW_F4 + 1]);

    float4 o;
    o.x = fmaxf(fmaxf(r0a.x, r0a.y), fmaxf(r1a.x, r1a.y));
    o.y = fmaxf(fmaxf(r0a.z, r0a.w), fmaxf(r1a.z, r1a.w));
    o.z = fmaxf(fmaxf(r0b.x, r0b.y), fmaxf(r1b.x, r1b.y));
    o.w = fmaxf(fmaxf(r0b.z, r0b.w), fmaxf(r1b.z, r1b.w));

    out4[tid] = o;
}

extern "C" void kernel_launch(void* const* d_in, const int* in_sizes, int n_in,
                              void* d_out, int out_size) {
    const float4* in4 = (const float4*)d_in[0];
    float4* out4 = (float4*)d_out;

    const unsigned total = (unsigned)BC * OUT_H * OUT_ROW_F4;  // 16,777,216
    const int threads = 64;
    const unsigned blocks = total / threads;                   // 262,144

    maxpool2x2_kernel<<<blocks, threads>>>(in4, out4);
}